// round 14
// baseline (speedup 1.0000x reference)
#include <cuda_runtime.h>
#include <cuda_bf16.h>
#include <math.h>
#include <stdint.h>

#define Sn 4
#define Nn 4096
#define Mn 4096
#define Dn 128
#define PAD 136        // bf16 elems per smem row: 272B stride, LDSM conflict-free
#define NCTA 296       // 2 x 148 SMs, exactly one balanced wave
#define NCHUNK 4096    // 128 panels x 32 M-chunks of 128 cols

// ---------------- scratch (__device__ globals; no allocation) ----------------
__device__ __align__(256) __nv_bfloat16 g_A[Sn * Nn * Dn];   // 4 MB
__device__ __align__(256) __nv_bfloat16 g_R[Sn * Mn * Dn];   // 4 MB
__device__ float g_pd[8][Sn * Nn];    // partial den  [(cta&3)*2+cg]
__device__ float g_pn[8][Sn * Nn];    // partial num
__device__ int   g_pp[8][Sn * Nn];    // partial n_pos
__device__ int   g_mask_u8;
__device__ float g_bsum[32];
__device__ int   g_bcnt[32];
__device__ int   g_done;

// ---------------- helpers ----------------
__device__ __forceinline__ uint32_t smem_u32(const void* p) {
    uint32_t a;
    asm("{ .reg .u64 t; cvta.to.shared.u64 t, %1; cvt.u32.u64 %0, t; }" : "=r"(a) : "l"(p));
    return a;
}
__device__ __forceinline__ float ex2f(float a) {
    float r; asm("ex2.approx.ftz.f32 %0, %1;" : "=f"(r) : "f"(a)); return r;
}
__device__ __forceinline__ void cp16(uint32_t dst, const void* src) {
    asm volatile("cp.async.cg.shared.global [%0], [%1], 16;" :: "r"(dst), "l"(src));
}
#define CP_COMMIT() asm volatile("cp.async.commit_group;" ::: "memory")
#define CP_WAIT(n)  asm volatile("cp.async.wait_group %0;" :: "n"(n) : "memory")

__device__ __forceinline__ void pfL2(const void* p) {
    asm volatile("prefetch.global.L2 [%0];" :: "l"(p));
}

__device__ __forceinline__ void ldsm4(uint32_t& r0, uint32_t& r1, uint32_t& r2,
                                      uint32_t& r3, uint32_t addr) {
    asm volatile("ldmatrix.sync.aligned.m8n8.x4.shared.b16 {%0,%1,%2,%3}, [%4];"
                 : "=r"(r0), "=r"(r1), "=r"(r2), "=r"(r3) : "r"(addr));
}
__device__ __forceinline__ void mma16816(float* c, uint32_t a0, uint32_t a1,
                                         uint32_t a2, uint32_t a3,
                                         uint32_t b0, uint32_t b1) {
    asm volatile(
        "mma.sync.aligned.m16n8k16.row.col.f32.bf16.bf16.f32 "
        "{%0,%1,%2,%3},{%4,%5,%6,%7},{%8,%9},{%0,%1,%2,%3};"
        : "+f"(c[0]), "+f"(c[1]), "+f"(c[2]), "+f"(c[3])
        : "r"(a0), "r"(a1), "r"(a2), "r"(a3), "r"(b0), "r"(b1));
}

// copy 128 rows x 128-bf16 tile (row-major, 256B rows) into PAD-layout smem
__device__ __forceinline__ void load_tileP(uint32_t dst, const char* src, int tid) {
    #pragma unroll
    for (int i = tid; i < 128 * 16; i += 256) {
        int r = i >> 4, cb = (i & 15) << 4;
        cp16(dst + r * (PAD * 2) + cb, src + r * 256 + cb);
    }
}
// R chunk for global chunk id cid: stem = cid>>10, M-offset = (cid&31)*128
__device__ __forceinline__ void load_R(uint32_t dst, int cid, int tid) {
    const char* src = (const char*)g_R
        + ((size_t)(cid >> 10) * Mn + (size_t)(cid & 31) * 128) * 256;
    load_tileP(dst, src, tid);
}

// ---------------- smem layout (dynamic) ----------------
#define SM_A   0
#define SM_R0  (128 * PAD * 2)              // 34816
#define SM_R1  (SM_R0 + 128 * PAD * 2)
#define SM_TOT (SM_R1 + 128 * PAD * 2)      // 104448 B; 2 CTAs/SM

// ---------------------------------------------------------------------------
// Kernel 0: zero partial slots + reset done counter + mask dtype probe
// (block 0 probes: int32 bools -> all words 0/1; uint8 -> some word > 1)
// ---------------------------------------------------------------------------
__global__ void zero_probe_kernel(const unsigned int* __restrict__ mw) {
    int i = blockIdx.x * 256 + threadIdx.x;   // 512*256 = 131072 entries
    if (i < 8 * Sn * Nn) {
        (&g_pd[0][0])[i] = 0.f;
        (&g_pn[0][0])[i] = 0.f;
        (&g_pp[0][0])[i] = 0;
    }
    if (blockIdx.x == 0) {
        __shared__ int any;
        if (threadIdx.x == 0) { any = 0; g_done = 0; }
        __syncthreads();
        int found = 0;
        for (int k = threadIdx.x; k < 4096; k += 256)
            if (mw[k] > 1u) found = 1;
        if (found) atomicOr(&any, 1);
        __syncthreads();
        if (threadIdx.x == 0) g_mask_u8 = any;
    }
}

// ---------------------------------------------------------------------------
// Kernel 1: L2-normalize rows -> bf16 (one warp per 128-float row)
// ---------------------------------------------------------------------------
__global__ void norm_kernel(const float* __restrict__ art,
                            const float* __restrict__ ref) {
    int row  = blockIdx.x * blockDim.y + threadIdx.y;
    int lane = threadIdx.x;
    const float* src;
    __nv_bfloat16* dst;
    if (row < Sn * Nn) {
        src = art + (size_t)row * Dn;
        dst = g_A + (size_t)row * Dn;
    } else {
        int r2 = row - Sn * Nn;
        src = ref + (size_t)r2 * Dn;
        dst = g_R + (size_t)r2 * Dn;
    }
    float4 v = reinterpret_cast<const float4*>(src)[lane];
    float ss = v.x * v.x + v.y * v.y + v.z * v.z + v.w * v.w;
    #pragma unroll
    for (int o = 16; o; o >>= 1) ss += __shfl_xor_sync(0xFFFFFFFFu, ss, o);
    float inv = 1.0f / fmaxf(sqrtf(ss), 1e-12f);
    __nv_bfloat162 p0 = __floats2bfloat162_rn(v.x * inv, v.y * inv);
    __nv_bfloat162 p1 = __floats2bfloat162_rn(v.z * inv, v.w * inv);
    reinterpret_cast<__nv_bfloat162*>(dst)[lane * 2 + 0] = p0;
    reinterpret_cast<__nv_bfloat162*>(dst)[lane * 2 + 1] = p1;
}

// launch-slot filler so the fused kernel sits at capture index 3
__global__ void dummy_kernel() {}

// ---------------------------------------------------------------------------
// Kernel 3: fused bf16 HMMA GEMM + fixed-offset exp-sum epilogue.
// 296 CTAs (one balanced wave at 2 CTAs/SM); CTA i owns the contiguous
// global-chunk range [i*4096/296, (i+1)*4096/296). 8 warps as 4 row-groups
// x 2 col-groups; warp tile 32 rows x 64 cols; R chunks of 128 refs,
// cp.async double-buffered; mask lines L2-prefetched two chunks ahead.
// ---------------------------------------------------------------------------
__global__ __launch_bounds__(256, 2)
void fused_kernel(const void* __restrict__ mask_raw,
                  const float* __restrict__ logT) {
    extern __shared__ char smem[];
    const uint32_t sb = smem_u32(smem);
    const int tid = threadIdx.x;
    const int w = tid >> 5, l = tid & 31;
    const int rg = w & 3, cg = w >> 2;           // row-group / col-group
    const int g = l >> 2, t2 = (l & 3) * 2;      // C-fragment row / col-pair
    const int lr = l & 7, sub = l >> 3;          // ldmatrix addressing
    const int cta = blockIdx.x;

    const int c0 = (cta * NCHUNK) / NCTA;
    const int c1 = ((cta + 1) * NCHUNK) / NCTA;

    const int mu8 = g_mask_u8;
    const float q  = __expf(-logT[0]) * 1.4426950408889634f;  // log2(e)/temp
    const float mC = -0.5f * q;                  // fixed exponent offset

    // A fragment bases (panel-independent offsets within SM_A)
    const uint32_t aBase0 =
        sb + SM_A + (uint32_t)(rg * 32 + lr + (sub & 1) * 8) * (PAD * 2) + (sub >> 1) * 16;
    const uint32_t aBase1 = aBase0 + 16 * (PAD * 2);
    const uint32_t bOff =
        (uint32_t)(cg * 64 + lr + (sub >> 1) * 8) * (PAD * 2) + (sub & 1) * 16;

    int cs = c0;
    while (cs < c1) {
        const int panel = cs >> 5;                       // 128 anchors each
        const int ce = min(c1, (panel + 1) << 5);        // segment end

        // this warp's per-lane prefetch row base (lane l covers row rg*32+l)
        const char* pfRow = (const char*)mask_raw
            + (size_t)(panel * 128 + rg * 32 + l) * Mn * 4 + (size_t)cg * 256;

        // ---- segment prologue: A panel + first R chunk(s) ----
        load_tileP(sb + SM_A, (const char*)g_A + (size_t)panel * 128 * 256, tid);
        load_R(sb + SM_R0, cs, tid);
        CP_COMMIT();
        if (!mu8) {                    // prefetch first two chunks' mask lines
            const char* p = pfRow + (size_t)(cs & 31) * 512;
            pfL2(p); pfL2(p + 128);
            if (cs + 1 < ce) {
                const char* p1 = pfRow + (size_t)((cs + 1) & 31) * 512;
                pfL2(p1); pfL2(p1 + 128);
            }
        }
        if (cs + 1 < ce) {
            load_R(sb + SM_R1, cs + 1, tid);
            CP_COMMIT();
            CP_WAIT(1);
        } else {
            CP_WAIT(0);
        }
        __syncthreads();

        float den[2][2] = {{0.f,0.f},{0.f,0.f}};   // [mt][j]
        float num[2][2] = {{0.f,0.f},{0.f,0.f}};
        int   np [2][2] = {{0,0},{0,0}};

        // mask row pointers for this panel (advance by chunk below)
        const char* mp[2][2];
        #pragma unroll
        for (int mt = 0; mt < 2; ++mt)
            #pragma unroll
            for (int j = 0; j < 2; ++j) {
                size_t elem = (size_t)(panel * 128 + rg * 32 + mt * 16 + g + j * 8) * Mn
                            + cg * 64 + t2;
                mp[mt][j] = (const char*)mask_raw + (mu8 ? elem : elem * 4);
            }

        for (int cid = cs; cid < ce; ++cid) {
            const int b = (cid - cs) & 1;
            const uint32_t sbR = sb + (b ? SM_R1 : SM_R0);

            // prefetch mask lines two chunks ahead (no regs, no deps)
            if (!mu8 && cid + 2 < ce) {
                const char* p = pfRow + (size_t)((cid + 2) & 31) * 512;
                pfL2(p); pfL2(p + 128);
            }

            float acc[2][8][4];
            #pragma unroll
            for (int mt = 0; mt < 2; ++mt)
                #pragma unroll
                for (int nt = 0; nt < 8; ++nt)
                    #pragma unroll
                    for (int k = 0; k < 4; ++k) acc[mt][nt][k] = 0.f;

            #pragma unroll
            for (int kt = 0; kt < 8; ++kt) {
                uint32_t a00, a01, a02, a03, a10, a11, a12, a13;
                ldsm4(a00, a01, a02, a03, aBase0 + kt * 32);
                ldsm4(a10, a11, a12, a13, aBase1 + kt * 32);
                #pragma unroll
                for (int i = 0; i < 4; ++i) {
                    uint32_t b0, b1, b2, b3;
                    ldsm4(b0, b1, b2, b3,
                          sbR + bOff + (uint32_t)i * 16 * (PAD * 2) + kt * 32);
                    mma16816(acc[0][2 * i],     a00, a01, a02, a03, b0, b1);
                    mma16816(acc[0][2 * i + 1], a00, a01, a02, a03, b2, b3);
                    mma16816(acc[1][2 * i],     a10, a11, a12, a13, b0, b1);
                    mma16816(acc[1][2 * i + 1], a10, a11, a12, a13, b2, b3);
                }
            }
            __syncthreads();              // all warps done reading R buffer b

            if (cid + 2 < ce) {           // prefetch R chunk cid+2 into freed buffer
                load_R(sbR, cid + 2, tid);
                CP_COMMIT();
            }

            // ---- epilogue: fixed-offset exp sums (4 rows x 16 cols/lane) ----
            const size_t moff = (size_t)(cid & 31) * (mu8 ? 128 : 512);
            #pragma unroll
            for (int mt = 0; mt < 2; ++mt)
                #pragma unroll
                for (int j = 0; j < 2; ++j) {
                    float d = den[mt][j], nu = num[mt][j];
                    int   cnt = np[mt][j];
                    const char* mr = mp[mt][j] + moff;
                    #pragma unroll
                    for (int nt = 0; nt < 8; ++nt) {
                        int m0, m1;
                        if (!mu8) {
                            int2 mm = *reinterpret_cast<const int2*>(mr + nt * 32);
                            m0 = mm.x; m1 = mm.y;
                        } else {
                            unsigned short mm =
                                *reinterpret_cast<const unsigned short*>(mr + nt * 8);
                            m0 = mm & 0x00FFu; m1 = mm & 0xFF00u;
                        }
                        float e0 = ex2f(fmaf(acc[mt][nt][2 * j],     q, mC));
                        float e1 = ex2f(fmaf(acc[mt][nt][2 * j + 1], q, mC));
                        // pair-sum first: halves the serial FADD chain depth
                        float es = e0 + e1;
                        float ns = (m0 ? e0 : 0.f) + (m1 ? e1 : 0.f);
                        int   cs2 = (m0 ? 1 : 0) + (m1 ? 1 : 0);
                        d += es; nu += ns; cnt += cs2;
                    }
                    den[mt][j] = d; num[mt][j] = nu; np[mt][j] = cnt;
                }

            if (cid + 2 < ce) CP_WAIT(1);
            else              CP_WAIT(0);
            __syncthreads();
        }

        // ---- quad reduce + write this panel's partials; slot=(cta&3)*2+cg ----
        const int part = (cta & 3) * 2 + cg;
        #pragma unroll
        for (int mt = 0; mt < 2; ++mt)
            #pragma unroll
            for (int j = 0; j < 2; ++j) {
                float d = den[mt][j], nu = num[mt][j];
                int cnt = np[mt][j];
                #pragma unroll
                for (int o = 1; o <= 2; o <<= 1) {
                    d   += __shfl_xor_sync(0xFFFFFFFFu, d, o);
                    nu  += __shfl_xor_sync(0xFFFFFFFFu, nu, o);
                    cnt += __shfl_xor_sync(0xFFFFFFFFu, cnt, o);
                }
                if ((l & 3) == 0) {
                    int idx = panel * 128 + rg * 32 + mt * 16 + g + j * 8;
                    g_pd[part][idx] = d;
                    g_pn[part][idx] = nu;
                    g_pp[part][idx] = cnt;
                }
            }
        __syncthreads();   // partials written before next segment reuses smem
        cs = ce;
    }
}

// ---------------------------------------------------------------------------
// Kernel 4: per-anchor combine + block partials; the LAST finished block
// aggregates to the scalar (order-invariant combine -> deterministic).
// ---------------------------------------------------------------------------
__global__ void stems_final_kernel(float* __restrict__ out) {
    __shared__ float sd[256];
    __shared__ int   sc[256];
    const int blk = blockIdx.x;
    const int s = blk >> 3, off = (blk & 7) * 512;
    float sum = 0.f; int cnt = 0;
    for (int i = threadIdx.x; i < 512; i += 256) {
        int idx = s * Nn + off + i;
        float d = 0.f, nu = 0.f; int p = 0;
        #pragma unroll
        for (int k = 0; k < 8; ++k) {
            d  += g_pd[k][idx];
            nu += g_pn[k][idx];
            p  += g_pp[k][idx];
        }
        if (p > 0 && p < Mn) { sum += __logf(d) - __logf(nu); cnt++; }
    }
    sd[threadIdx.x] = sum; sc[threadIdx.x] = cnt;
    __syncthreads();
    for (int o = 128; o; o >>= 1) {
        if (threadIdx.x < o) {
            sd[threadIdx.x] += sd[threadIdx.x + o];
            sc[threadIdx.x] += sc[threadIdx.x + o];
        }
        __syncthreads();
    }
    if (threadIdx.x == 0) {
        g_bsum[blk] = sd[0]; g_bcnt[blk] = sc[0];
        __threadfence();
        if (atomicAdd(&g_done, 1) == 31) {   // last block aggregates
            float loss = 0.f; int ns = 0;
            #pragma unroll
            for (int st = 0; st < Sn; ++st) {
                float ssum = 0.f; int scnt = 0;
                #pragma unroll
                for (int b2 = 0; b2 < 8; ++b2) {
                    ssum += g_bsum[st * 8 + b2];
                    scnt += g_bcnt[st * 8 + b2];
                }
                if (scnt > 0) { loss += ssum / (float)scnt; ns++; }
            }
            out[0] = ns > 0 ? loss / (float)ns : 0.f;
        }
    }
}

// ---------------------------------------------------------------------------
extern "C" void kernel_launch(void* const* d_in, const int* in_sizes, int n_in,
                              void* d_out, int out_size) {
    const float* art  = (const float*)d_in[0];
    const float* ref  = (const float*)d_in[1];
    const void*  mask = d_in[2];
    const float* logT = (const float*)d_in[3];
    (void)in_sizes; (void)n_in; (void)out_size;

    cudaFuncSetAttribute(fused_kernel,
                         cudaFuncAttributeMaxDynamicSharedMemorySize, SM_TOT);

    zero_probe_kernel<<<512, 256>>>((const unsigned int*)mask);   // idx 0
    norm_kernel<<<(Sn * (Nn + Mn)) / 8, dim3(32, 8)>>>(art, ref); // idx 1
    dummy_kernel<<<1, 32>>>();                                    // idx 2
    fused_kernel<<<NCTA, 256, SM_TOT>>>(mask, logT);              // idx 3
    stems_final_kernel<<<32, 256>>>((float*)d_out);               // idx 4
}

// round 15
// speedup vs baseline: 1.0738x; 1.0738x over previous
#include <cuda_runtime.h>
#include <cuda_bf16.h>
#include <math.h>
#include <stdint.h>

#define Sn 4
#define Nn 4096
#define Mn 4096
#define Dn 128
#define PAD 136        // bf16 elems per smem row: 272B stride, LDSM conflict-free
#define NCTA 296       // 2 x 148 SMs, exactly one balanced wave
#define NCHUNK 4096    // 128 panels x 32 M-chunks of 128 cols

// ---------------- scratch (__device__ globals; no allocation) ----------------
__device__ __align__(256) __nv_bfloat16 g_A[Sn * Nn * Dn];   // 4 MB
__device__ __align__(256) __nv_bfloat16 g_R[Sn * Mn * Dn];   // 4 MB
__device__ float g_pd[8][Sn * Nn];    // partial den  [(cta&3)*2+cg]
__device__ float g_pn[8][Sn * Nn];    // partial num
__device__ int   g_pp[8][Sn * Nn];    // partial n_pos
__device__ int   g_mask_u8;
__device__ float g_bsum[32];
__device__ int   g_bcnt[32];
__device__ int   g_done;

// ---------------- helpers ----------------
__device__ __forceinline__ uint32_t smem_u32(const void* p) {
    uint32_t a;
    asm("{ .reg .u64 t; cvta.to.shared.u64 t, %1; cvt.u32.u64 %0, t; }" : "=r"(a) : "l"(p));
    return a;
}
__device__ __forceinline__ float ex2f(float a) {
    float r; asm("ex2.approx.ftz.f32 %0, %1;" : "=f"(r) : "f"(a)); return r;
}
__device__ __forceinline__ void cp16(uint32_t dst, const void* src) {
    asm volatile("cp.async.cg.shared.global [%0], [%1], 16;" :: "r"(dst), "l"(src));
}
#define CP_COMMIT() asm volatile("cp.async.commit_group;" ::: "memory")
#define CP_WAIT(n)  asm volatile("cp.async.wait_group %0;" :: "n"(n) : "memory")

__device__ __forceinline__ void pfL2(const void* p) {
    asm volatile("prefetch.global.L2 [%0];" :: "l"(p));
}

__device__ __forceinline__ void ldsm4(uint32_t& r0, uint32_t& r1, uint32_t& r2,
                                      uint32_t& r3, uint32_t addr) {
    asm volatile("ldmatrix.sync.aligned.m8n8.x4.shared.b16 {%0,%1,%2,%3}, [%4];"
                 : "=r"(r0), "=r"(r1), "=r"(r2), "=r"(r3) : "r"(addr));
}
__device__ __forceinline__ void mma16816(float* c, uint32_t a0, uint32_t a1,
                                         uint32_t a2, uint32_t a3,
                                         uint32_t b0, uint32_t b1) {
    asm volatile(
        "mma.sync.aligned.m16n8k16.row.col.f32.bf16.bf16.f32 "
        "{%0,%1,%2,%3},{%4,%5,%6,%7},{%8,%9},{%0,%1,%2,%3};"
        : "+f"(c[0]), "+f"(c[1]), "+f"(c[2]), "+f"(c[3])
        : "r"(a0), "r"(a1), "r"(a2), "r"(a3), "r"(b0), "r"(b1));
}

// copy 128 rows x 128-bf16 tile (row-major, 256B rows) into PAD-layout smem
__device__ __forceinline__ void load_tileP(uint32_t dst, const char* src, int tid) {
    #pragma unroll
    for (int i = tid; i < 128 * 16; i += 256) {
        int r = i >> 4, cb = (i & 15) << 4;
        cp16(dst + r * (PAD * 2) + cb, src + r * 256 + cb);
    }
}
// R chunk for global chunk id cid: stem = cid>>10, M-offset = (cid&31)*128
__device__ __forceinline__ void load_R(uint32_t dst, int cid, int tid) {
    const char* src = (const char*)g_R
        + ((size_t)(cid >> 10) * Mn + (size_t)(cid & 31) * 128) * 256;
    load_tileP(dst, src, tid);
}

// ---------------- smem layout (dynamic) ----------------
#define SM_A   0
#define SM_R0  (128 * PAD * 2)              // 34816
#define SM_R1  (SM_R0 + 128 * PAD * 2)
#define SM_TOT (SM_R1 + 128 * PAD * 2)      // 104448 B; 2 CTAs/SM

// ---------------------------------------------------------------------------
// Kernel 0: zero partial slots + reset done counter + mask dtype probe
// (block 0 probes: int32 bools -> all words 0/1; uint8 -> some word > 1)
// ---------------------------------------------------------------------------
__global__ void zero_probe_kernel(const unsigned int* __restrict__ mw) {
    int i = blockIdx.x * 256 + threadIdx.x;   // 512*256 = 131072 entries
    if (i < 8 * Sn * Nn) {
        (&g_pd[0][0])[i] = 0.f;
        (&g_pn[0][0])[i] = 0.f;
        (&g_pp[0][0])[i] = 0;
    }
    if (blockIdx.x == 0) {
        __shared__ int any;
        if (threadIdx.x == 0) { any = 0; g_done = 0; }
        __syncthreads();
        int found = 0;
        for (int k = threadIdx.x; k < 4096; k += 256)
            if (mw[k] > 1u) found = 1;
        if (found) atomicOr(&any, 1);
        __syncthreads();
        if (threadIdx.x == 0) g_mask_u8 = any;
    }
}

// ---------------------------------------------------------------------------
// Kernel 1: L2-normalize rows -> bf16 (one warp per 128-float row)
// ---------------------------------------------------------------------------
__global__ void norm_kernel(const float* __restrict__ art,
                            const float* __restrict__ ref) {
    int row  = blockIdx.x * blockDim.y + threadIdx.y;
    int lane = threadIdx.x;
    const float* src;
    __nv_bfloat16* dst;
    if (row < Sn * Nn) {
        src = art + (size_t)row * Dn;
        dst = g_A + (size_t)row * Dn;
    } else {
        int r2 = row - Sn * Nn;
        src = ref + (size_t)r2 * Dn;
        dst = g_R + (size_t)r2 * Dn;
    }
    float4 v = reinterpret_cast<const float4*>(src)[lane];
    float ss = v.x * v.x + v.y * v.y + v.z * v.z + v.w * v.w;
    #pragma unroll
    for (int o = 16; o; o >>= 1) ss += __shfl_xor_sync(0xFFFFFFFFu, ss, o);
    float inv = 1.0f / fmaxf(sqrtf(ss), 1e-12f);
    __nv_bfloat162 p0 = __floats2bfloat162_rn(v.x * inv, v.y * inv);
    __nv_bfloat162 p1 = __floats2bfloat162_rn(v.z * inv, v.w * inv);
    reinterpret_cast<__nv_bfloat162*>(dst)[lane * 2 + 0] = p0;
    reinterpret_cast<__nv_bfloat162*>(dst)[lane * 2 + 1] = p1;
}

// launch-slot filler so the fused kernel sits at capture index 3
__global__ void dummy_kernel() {}

// ---------------------------------------------------------------------------
// Kernel 3: fused bf16 HMMA GEMM + fixed-offset exp-sum epilogue.
// 296 CTAs (one balanced wave at 2 CTAs/SM); CTA i owns the contiguous
// global-chunk range [i*4096/296, (i+1)*4096/296). 8 warps as 4 row-groups
// x 2 col-groups; warp tile 32 rows x 64 cols; R chunks of 128 refs,
// cp.async double-buffered; mask lines L2-prefetched ONE chunk ahead
// (distance 2 measured as L2-thrash: +67MB DRAM). 2 CTAs/SM.
// ---------------------------------------------------------------------------
__global__ __launch_bounds__(256, 2)
void fused_kernel(const void* __restrict__ mask_raw,
                  const float* __restrict__ logT) {
    extern __shared__ char smem[];
    const uint32_t sb = smem_u32(smem);
    const int tid = threadIdx.x;
    const int w = tid >> 5, l = tid & 31;
    const int rg = w & 3, cg = w >> 2;           // row-group / col-group
    const int g = l >> 2, t2 = (l & 3) * 2;      // C-fragment row / col-pair
    const int lr = l & 7, sub = l >> 3;          // ldmatrix addressing
    const int cta = blockIdx.x;

    const int c0 = (cta * NCHUNK) / NCTA;
    const int c1 = ((cta + 1) * NCHUNK) / NCTA;

    const int mu8 = g_mask_u8;
    const float q  = __expf(-logT[0]) * 1.4426950408889634f;  // log2(e)/temp
    const float mC = -0.5f * q;                  // fixed exponent offset

    // A fragment bases (panel-independent offsets within SM_A)
    const uint32_t aBase0 =
        sb + SM_A + (uint32_t)(rg * 32 + lr + (sub & 1) * 8) * (PAD * 2) + (sub >> 1) * 16;
    const uint32_t aBase1 = aBase0 + 16 * (PAD * 2);
    const uint32_t bOff =
        (uint32_t)(cg * 64 + lr + (sub >> 1) * 8) * (PAD * 2) + (sub & 1) * 16;

    int cs = c0;
    while (cs < c1) {
        const int panel = cs >> 5;                       // 128 anchors each
        const int ce = min(c1, (panel + 1) << 5);        // segment end

        // this warp's per-lane prefetch row base (lane l covers row rg*32+l)
        const char* pfRow = (const char*)mask_raw
            + (size_t)(panel * 128 + rg * 32 + l) * Mn * 4 + (size_t)cg * 256;

        // ---- segment prologue: A panel + first R chunk(s) ----
        load_tileP(sb + SM_A, (const char*)g_A + (size_t)panel * 128 * 256, tid);
        load_R(sb + SM_R0, cs, tid);
        CP_COMMIT();
        if (!mu8) {                                  // prefetch first chunk's mask
            const char* p = pfRow + (size_t)(cs & 31) * 512;
            pfL2(p); pfL2(p + 128);
        }
        if (cs + 1 < ce) {
            load_R(sb + SM_R1, cs + 1, tid);
            CP_COMMIT();
            CP_WAIT(1);
        } else {
            CP_WAIT(0);
        }
        __syncthreads();

        float den[2][2] = {{0.f,0.f},{0.f,0.f}};   // [mt][j]
        float num[2][2] = {{0.f,0.f},{0.f,0.f}};
        int   np [2][2] = {{0,0},{0,0}};

        // mask row pointers for this panel (advance by chunk below)
        const char* mp[2][2];
        #pragma unroll
        for (int mt = 0; mt < 2; ++mt)
            #pragma unroll
            for (int j = 0; j < 2; ++j) {
                size_t elem = (size_t)(panel * 128 + rg * 32 + mt * 16 + g + j * 8) * Mn
                            + cg * 64 + t2;
                mp[mt][j] = (const char*)mask_raw + (mu8 ? elem : elem * 4);
            }

        for (int cid = cs; cid < ce; ++cid) {
            const int b = (cid - cs) & 1;
            const uint32_t sbR = sb + (b ? SM_R1 : SM_R0);

            // prefetch next chunk's mask lines into L2 (no regs, no deps)
            if (!mu8 && cid + 1 < ce) {
                const char* p = pfRow + (size_t)((cid + 1) & 31) * 512;
                pfL2(p); pfL2(p + 128);
            }

            float acc[2][8][4];
            #pragma unroll
            for (int mt = 0; mt < 2; ++mt)
                #pragma unroll
                for (int nt = 0; nt < 8; ++nt)
                    #pragma unroll
                    for (int k = 0; k < 4; ++k) acc[mt][nt][k] = 0.f;

            #pragma unroll
            for (int kt = 0; kt < 8; ++kt) {
                uint32_t a00, a01, a02, a03, a10, a11, a12, a13;
                ldsm4(a00, a01, a02, a03, aBase0 + kt * 32);
                ldsm4(a10, a11, a12, a13, aBase1 + kt * 32);
                #pragma unroll
                for (int i = 0; i < 4; ++i) {
                    uint32_t b0, b1, b2, b3;
                    ldsm4(b0, b1, b2, b3,
                          sbR + bOff + (uint32_t)i * 16 * (PAD * 2) + kt * 32);
                    mma16816(acc[0][2 * i],     a00, a01, a02, a03, b0, b1);
                    mma16816(acc[0][2 * i + 1], a00, a01, a02, a03, b2, b3);
                    mma16816(acc[1][2 * i],     a10, a11, a12, a13, b0, b1);
                    mma16816(acc[1][2 * i + 1], a10, a11, a12, a13, b2, b3);
                }
            }
            __syncthreads();              // all warps done reading R buffer b

            if (cid + 2 < ce) {           // prefetch R chunk cid+2 into freed buffer
                load_R(sbR, cid + 2, tid);
                CP_COMMIT();
            }

            // ---- epilogue: fixed-offset exp sums (4 rows x 16 cols/lane) ----
            const size_t moff = (size_t)(cid & 31) * (mu8 ? 128 : 512);
            #pragma unroll
            for (int mt = 0; mt < 2; ++mt)
                #pragma unroll
                for (int j = 0; j < 2; ++j) {
                    float d = den[mt][j], nu = num[mt][j];
                    int   cnt = np[mt][j];
                    const char* mr = mp[mt][j] + moff;
                    #pragma unroll
                    for (int nt = 0; nt < 8; ++nt) {
                        int m0, m1;
                        if (!mu8) {
                            int2 mm = *reinterpret_cast<const int2*>(mr + nt * 32);
                            m0 = mm.x; m1 = mm.y;
                        } else {
                            unsigned short mm =
                                *reinterpret_cast<const unsigned short*>(mr + nt * 8);
                            m0 = mm & 0x00FFu; m1 = mm & 0xFF00u;
                        }
                        float e0 = ex2f(fmaf(acc[mt][nt][2 * j],     q, mC));
                        float e1 = ex2f(fmaf(acc[mt][nt][2 * j + 1], q, mC));
                        d += e0 + e1;
                        if (m0) { nu += e0; cnt++; }
                        if (m1) { nu += e1; cnt++; }
                    }
                    den[mt][j] = d; num[mt][j] = nu; np[mt][j] = cnt;
                }

            if (cid + 2 < ce) CP_WAIT(1);
            else              CP_WAIT(0);
            __syncthreads();
        }

        // ---- quad reduce + write this panel's partials; slot=(cta&3)*2+cg ----
        const int part = (cta & 3) * 2 + cg;
        #pragma unroll
        for (int mt = 0; mt < 2; ++mt)
            #pragma unroll
            for (int j = 0; j < 2; ++j) {
                float d = den[mt][j], nu = num[mt][j];
                int cnt = np[mt][j];
                #pragma unroll
                for (int o = 1; o <= 2; o <<= 1) {
                    d   += __shfl_xor_sync(0xFFFFFFFFu, d, o);
                    nu  += __shfl_xor_sync(0xFFFFFFFFu, nu, o);
                    cnt += __shfl_xor_sync(0xFFFFFFFFu, cnt, o);
                }
                if ((l & 3) == 0) {
                    int idx = panel * 128 + rg * 32 + mt * 16 + g + j * 8;
                    g_pd[part][idx] = d;
                    g_pn[part][idx] = nu;
                    g_pp[part][idx] = cnt;
                }
            }
        __syncthreads();   // partials written before next segment reuses smem
        cs = ce;
    }
}

// ---------------------------------------------------------------------------
// Kernel 4: per-anchor combine + block partials; the LAST finished block
// aggregates to the scalar (order-invariant combine -> deterministic).
// ---------------------------------------------------------------------------
__global__ void stems_final_kernel(float* __restrict__ out) {
    __shared__ float sd[256];
    __shared__ int   sc[256];
    const int blk = blockIdx.x;
    const int s = blk >> 3, off = (blk & 7) * 512;
    float sum = 0.f; int cnt = 0;
    for (int i = threadIdx.x; i < 512; i += 256) {
        int idx = s * Nn + off + i;
        float d = 0.f, nu = 0.f; int p = 0;
        #pragma unroll
        for (int k = 0; k < 8; ++k) {
            d  += g_pd[k][idx];
            nu += g_pn[k][idx];
            p  += g_pp[k][idx];
        }
        if (p > 0 && p < Mn) { sum += __logf(d) - __logf(nu); cnt++; }
    }
    sd[threadIdx.x] = sum; sc[threadIdx.x] = cnt;
    __syncthreads();
    for (int o = 128; o; o >>= 1) {
        if (threadIdx.x < o) {
            sd[threadIdx.x] += sd[threadIdx.x + o];
            sc[threadIdx.x] += sc[threadIdx.x + o];
        }
        __syncthreads();
    }
    if (threadIdx.x == 0) {
        g_bsum[blk] = sd[0]; g_bcnt[blk] = sc[0];
        __threadfence();
        if (atomicAdd(&g_done, 1) == 31) {   // last block aggregates
            float loss = 0.f; int ns = 0;
            #pragma unroll
            for (int st = 0; st < Sn; ++st) {
                float ssum = 0.f; int scnt = 0;
                #pragma unroll
                for (int b2 = 0; b2 < 8; ++b2) {
                    ssum += g_bsum[st * 8 + b2];
                    scnt += g_bcnt[st * 8 + b2];
                }
                if (scnt > 0) { loss += ssum / (float)scnt; ns++; }
            }
            out[0] = ns > 0 ? loss / (float)ns : 0.f;
        }
    }
}

// ---------------------------------------------------------------------------
extern "C" void kernel_launch(void* const* d_in, const int* in_sizes, int n_in,
                              void* d_out, int out_size) {
    const float* art  = (const float*)d_in[0];
    const float* ref  = (const float*)d_in[1];
    const void*  mask = d_in[2];
    const float* logT = (const float*)d_in[3];
    (void)in_sizes; (void)n_in; (void)out_size;

    cudaFuncSetAttribute(fused_kernel,
                         cudaFuncAttributeMaxDynamicSharedMemorySize, SM_TOT);

    zero_probe_kernel<<<512, 256>>>((const unsigned int*)mask);   // idx 0
    norm_kernel<<<(Sn * (Nn + Mn)) / 8, dim3(32, 8)>>>(art, ref); // idx 1
    dummy_kernel<<<1, 32>>>();                                    // idx 2
    fused_kernel<<<NCTA, 256, SM_TOT>>>(mask, logT);              // idx 3
    stems_final_kernel<<<32, 256>>>((float*)d_out);               // idx 4
}

// round 16
// speedup vs baseline: 1.1768x; 1.0960x over previous
#include <cuda_runtime.h>
#include <cuda_bf16.h>
#include <math.h>
#include <stdint.h>

#define Sn 4
#define Nn 4096
#define Mn 4096
#define Dn 128
#define PAD 136        // bf16 elems per smem row: 272B stride, LDSM conflict-free
#define NCTA 296       // 2 x 148 SMs, exactly one balanced wave
#define NCHUNK 4096    // 128 panels x 32 M-chunks of 128 cols

// ---------------- scratch (__device__ globals; no allocation) ----------------
__device__ __align__(256) __nv_bfloat16 g_A[Sn * Nn * Dn];   // 4 MB
__device__ __align__(256) __nv_bfloat16 g_R[Sn * Mn * Dn];   // 4 MB
__device__ float g_pd[8][Sn * Nn];    // partial den  [(cta&3)*2+cg]
__device__ float g_pn[8][Sn * Nn];    // partial num
__device__ int   g_pp[8][Sn * Nn];    // partial n_pos
__device__ int   g_mask_u8;
__device__ float g_bsum[32];
__device__ int   g_bcnt[32];

// ---------------- helpers ----------------
__device__ __forceinline__ uint32_t smem_u32(const void* p) {
    uint32_t a;
    asm("{ .reg .u64 t; cvta.to.shared.u64 t, %1; cvt.u32.u64 %0, t; }" : "=r"(a) : "l"(p));
    return a;
}
__device__ __forceinline__ float ex2f(float a) {
    float r; asm("ex2.approx.ftz.f32 %0, %1;" : "=f"(r) : "f"(a)); return r;
}
__device__ __forceinline__ void cp16(uint32_t dst, const void* src) {
    asm volatile("cp.async.cg.shared.global [%0], [%1], 16;" :: "r"(dst), "l"(src));
}
#define CP_COMMIT() asm volatile("cp.async.commit_group;" ::: "memory")
#define CP_WAIT(n)  asm volatile("cp.async.wait_group %0;" :: "n"(n) : "memory")

// split-phase block barrier: 256 threads x (arrive + sync) -> count 512
#define BAR_ARRIVE() asm volatile("bar.arrive 1, 512;" ::: "memory")
#define BAR_WAIT()   asm volatile("bar.sync 1, 512;" ::: "memory")

__device__ __forceinline__ void pfL2(const void* p) {
    asm volatile("prefetch.global.L2 [%0];" :: "l"(p));
}

__device__ __forceinline__ void ldsm4(uint32_t& r0, uint32_t& r1, uint32_t& r2,
                                      uint32_t& r3, uint32_t addr) {
    asm volatile("ldmatrix.sync.aligned.m8n8.x4.shared.b16 {%0,%1,%2,%3}, [%4];"
                 : "=r"(r0), "=r"(r1), "=r"(r2), "=r"(r3) : "r"(addr));
}
__device__ __forceinline__ void mma16816(float* c, uint32_t a0, uint32_t a1,
                                         uint32_t a2, uint32_t a3,
                                         uint32_t b0, uint32_t b1) {
    asm volatile(
        "mma.sync.aligned.m16n8k16.row.col.f32.bf16.bf16.f32 "
        "{%0,%1,%2,%3},{%4,%5,%6,%7},{%8,%9},{%0,%1,%2,%3};"
        : "+f"(c[0]), "+f"(c[1]), "+f"(c[2]), "+f"(c[3])
        : "r"(a0), "r"(a1), "r"(a2), "r"(a3), "r"(b0), "r"(b1));
}

// copy 128 rows x 128-bf16 tile (row-major, 256B rows) into PAD-layout smem
__device__ __forceinline__ void load_tileP(uint32_t dst, const char* src, int tid) {
    #pragma unroll
    for (int i = tid; i < 128 * 16; i += 256) {
        int r = i >> 4, cb = (i & 15) << 4;
        cp16(dst + r * (PAD * 2) + cb, src + r * 256 + cb);
    }
}
// R chunk for global chunk id cid: stem = cid>>10, M-offset = (cid&31)*128
__device__ __forceinline__ void load_R(uint32_t dst, int cid, int tid) {
    const char* src = (const char*)g_R
        + ((size_t)(cid >> 10) * Mn + (size_t)(cid & 31) * 128) * 256;
    load_tileP(dst, src, tid);
}

// ---------------- smem layout (dynamic) ----------------
#define SM_A   0
#define SM_R0  (128 * PAD * 2)              // 34816
#define SM_R1  (SM_R0 + 128 * PAD * 2)
#define SM_TOT (SM_R1 + 128 * PAD * 2)      // 104448 B; 2 CTAs/SM

// ---------------------------------------------------------------------------
// Kernel 0: mask dtype probe (int32 bools -> all words 0/1; uint8 -> not)
// ---------------------------------------------------------------------------
__global__ void probe_mask_kernel(const unsigned int* __restrict__ mw) {
    __shared__ int any;
    if (threadIdx.x == 0) any = 0;
    __syncthreads();
    int found = 0;
    for (int i = threadIdx.x; i < 4096; i += blockDim.x)
        if (mw[i] > 1u) found = 1;
    if (found) atomicOr(&any, 1);
    __syncthreads();
    if (threadIdx.x == 0) g_mask_u8 = any;
}

// ---------------------------------------------------------------------------
// Kernel 1: L2-normalize rows -> bf16 (one warp per 128-float row)
// ---------------------------------------------------------------------------
__global__ void norm_kernel(const float* __restrict__ art,
                            const float* __restrict__ ref) {
    int row  = blockIdx.x * blockDim.y + threadIdx.y;
    int lane = threadIdx.x;
    const float* src;
    __nv_bfloat16* dst;
    if (row < Sn * Nn) {
        src = art + (size_t)row * Dn;
        dst = g_A + (size_t)row * Dn;
    } else {
        int r2 = row - Sn * Nn;
        src = ref + (size_t)r2 * Dn;
        dst = g_R + (size_t)r2 * Dn;
    }
    float4 v = reinterpret_cast<const float4*>(src)[lane];
    float ss = v.x * v.x + v.y * v.y + v.z * v.z + v.w * v.w;
    #pragma unroll
    for (int o = 16; o; o >>= 1) ss += __shfl_xor_sync(0xFFFFFFFFu, ss, o);
    float inv = 1.0f / fmaxf(sqrtf(ss), 1e-12f);
    __nv_bfloat162 p0 = __floats2bfloat162_rn(v.x * inv, v.y * inv);
    __nv_bfloat162 p1 = __floats2bfloat162_rn(v.z * inv, v.w * inv);
    reinterpret_cast<__nv_bfloat162*>(dst)[lane * 2 + 0] = p0;
    reinterpret_cast<__nv_bfloat162*>(dst)[lane * 2 + 1] = p1;
}

// ---------------------------------------------------------------------------
// Kernel 2: zero partial-slot arrays (also the launch-idx-2 filler so the
// fused kernel stays at ncu capture index 3)
// ---------------------------------------------------------------------------
__global__ void zero_kernel() {
    int i = blockIdx.x * 256 + threadIdx.x;   // 8*16384 = 131072 entries
    if (i < 8 * Sn * Nn) {
        (&g_pd[0][0])[i] = 0.f;
        (&g_pn[0][0])[i] = 0.f;
        (&g_pp[0][0])[i] = 0;
    }
}

// ---------------------------------------------------------------------------
// Kernel 3: fused bf16 HMMA GEMM + fixed-offset exp-sum epilogue.
// 296 CTAs (one balanced wave at 2 CTAs/SM); CTA i owns the contiguous
// global-chunk range [i*4096/296, (i+1)*4096/296). 8 warps as 4 row-groups
// x 2 col-groups; warp tile 32 rows x 64 cols; R chunks of 128 refs,
// cp.async double-buffered; mask lines L2-prefetched one chunk ahead.
// Split-phase barrier: warps arrive after mma, run the epilogue (no smem
// deps), and only wait before the buffer overwrite -> inter-warp skew is
// absorbed by epilogue work instead of barrier idle.
// ---------------------------------------------------------------------------
__global__ __launch_bounds__(256, 2)
void fused_kernel(const void* __restrict__ mask_raw,
                  const float* __restrict__ logT) {
    extern __shared__ char smem[];
    const uint32_t sb = smem_u32(smem);
    const int tid = threadIdx.x;
    const int w = tid >> 5, l = tid & 31;
    const int rg = w & 3, cg = w >> 2;           // row-group / col-group
    const int g = l >> 2, t2 = (l & 3) * 2;      // C-fragment row / col-pair
    const int lr = l & 7, sub = l >> 3;          // ldmatrix addressing
    const int cta = blockIdx.x;

    const int c0 = (cta * NCHUNK) / NCTA;
    const int c1 = ((cta + 1) * NCHUNK) / NCTA;

    const int mu8 = g_mask_u8;
    const float q  = __expf(-logT[0]) * 1.4426950408889634f;  // log2(e)/temp
    const float mC = -0.5f * q;                  // fixed exponent offset

    // A fragment bases (panel-independent offsets within SM_A)
    const uint32_t aBase0 =
        sb + SM_A + (uint32_t)(rg * 32 + lr + (sub & 1) * 8) * (PAD * 2) + (sub >> 1) * 16;
    const uint32_t aBase1 = aBase0 + 16 * (PAD * 2);
    const uint32_t bOff =
        (uint32_t)(cg * 64 + lr + (sub >> 1) * 8) * (PAD * 2) + (sub & 1) * 16;

    int cs = c0;
    while (cs < c1) {
        const int panel = cs >> 5;                       // 128 anchors each
        const int ce = min(c1, (panel + 1) << 5);        // segment end

        // this warp's per-lane prefetch row base (lane l covers row rg*32+l)
        const char* pfRow = (const char*)mask_raw
            + (size_t)(panel * 128 + rg * 32 + l) * Mn * 4 + (size_t)cg * 256;

        // ---- segment prologue: A panel + first R chunk(s) ----
        load_tileP(sb + SM_A, (const char*)g_A + (size_t)panel * 128 * 256, tid);
        load_R(sb + SM_R0, cs, tid);
        CP_COMMIT();
        if (!mu8) {                                  // prefetch first chunk's mask
            const char* p = pfRow + (size_t)(cs & 31) * 512;
            pfL2(p); pfL2(p + 128);
        }
        if (cs + 1 < ce) {
            load_R(sb + SM_R1, cs + 1, tid);
            CP_COMMIT();
            CP_WAIT(1);
        } else {
            CP_WAIT(0);
        }
        __syncthreads();

        float den[2][2] = {{0.f,0.f},{0.f,0.f}};   // [mt][j]
        float num[2][2] = {{0.f,0.f},{0.f,0.f}};
        int   np [2][2] = {{0,0},{0,0}};

        // mask row pointers for this panel (advance by chunk below)
        const char* mp[2][2];
        #pragma unroll
        for (int mt = 0; mt < 2; ++mt)
            #pragma unroll
            for (int j = 0; j < 2; ++j) {
                size_t elem = (size_t)(panel * 128 + rg * 32 + mt * 16 + g + j * 8) * Mn
                            + cg * 64 + t2;
                mp[mt][j] = (const char*)mask_raw + (mu8 ? elem : elem * 4);
            }

        for (int cid = cs; cid < ce; ++cid) {
            const int b = (cid - cs) & 1;
            const uint32_t sbR = sb + (b ? SM_R1 : SM_R0);

            // prefetch next chunk's mask lines into L2 (no regs, no deps)
            if (!mu8 && cid + 1 < ce) {
                const char* p = pfRow + (size_t)((cid + 1) & 31) * 512;
                pfL2(p); pfL2(p + 128);
            }

            float acc[2][8][4];
            #pragma unroll
            for (int mt = 0; mt < 2; ++mt)
                #pragma unroll
                for (int nt = 0; nt < 8; ++nt)
                    #pragma unroll
                    for (int k = 0; k < 4; ++k) acc[mt][nt][k] = 0.f;

            #pragma unroll
            for (int kt = 0; kt < 8; ++kt) {
                uint32_t a00, a01, a02, a03, a10, a11, a12, a13;
                ldsm4(a00, a01, a02, a03, aBase0 + kt * 32);
                ldsm4(a10, a11, a12, a13, aBase1 + kt * 32);
                #pragma unroll
                for (int i = 0; i < 4; ++i) {
                    uint32_t b0, b1, b2, b3;
                    ldsm4(b0, b1, b2, b3,
                          sbR + bOff + (uint32_t)i * 16 * (PAD * 2) + kt * 32);
                    mma16816(acc[0][2 * i],     a00, a01, a02, a03, b0, b1);
                    mma16816(acc[0][2 * i + 1], a00, a01, a02, a03, b2, b3);
                    mma16816(acc[1][2 * i],     a10, a11, a12, a13, b0, b1);
                    mma16816(acc[1][2 * i + 1], a10, a11, a12, a13, b2, b3);
                }
            }
            BAR_ARRIVE();                 // signal: this warp done reading buf b

            // ---- epilogue: fixed-offset exp sums (4 rows x 16 cols/lane) ----
            // (registers + global mask only -> safe before the barrier wait)
            const size_t moff = (size_t)(cid & 31) * (mu8 ? 128 : 512);
            #pragma unroll
            for (int mt = 0; mt < 2; ++mt)
                #pragma unroll
                for (int j = 0; j < 2; ++j) {
                    float d = den[mt][j], nu = num[mt][j];
                    int   cnt = np[mt][j];
                    const char* mr = mp[mt][j] + moff;
                    #pragma unroll
                    for (int nt = 0; nt < 8; ++nt) {
                        int m0, m1;
                        if (!mu8) {
                            int2 mm = *reinterpret_cast<const int2*>(mr + nt * 32);
                            m0 = mm.x; m1 = mm.y;
                        } else {
                            unsigned short mm =
                                *reinterpret_cast<const unsigned short*>(mr + nt * 8);
                            m0 = mm & 0x00FFu; m1 = mm & 0xFF00u;
                        }
                        float e0 = ex2f(fmaf(acc[mt][nt][2 * j],     q, mC));
                        float e1 = ex2f(fmaf(acc[mt][nt][2 * j + 1], q, mC));
                        d += e0 + e1;
                        if (m0) { nu += e0; cnt++; }
                        if (m1) { nu += e1; cnt++; }
                    }
                    den[mt][j] = d; num[mt][j] = nu; np[mt][j] = cnt;
                }

            BAR_WAIT();                   // all warps done reading buf b

            if (cid + 2 < ce) {           // prefetch R chunk cid+2 into freed buffer
                load_R(sbR, cid + 2, tid);
                CP_COMMIT();
                CP_WAIT(1);
            } else {
                CP_WAIT(0);
            }
            __syncthreads();              // chunk cid+1 visible to all threads
        }

        // ---- quad reduce + write this panel's partials; slot=(cta&3)*2+cg ----
        const int part = (cta & 3) * 2 + cg;
        #pragma unroll
        for (int mt = 0; mt < 2; ++mt)
            #pragma unroll
            for (int j = 0; j < 2; ++j) {
                float d = den[mt][j], nu = num[mt][j];
                int cnt = np[mt][j];
                #pragma unroll
                for (int o = 1; o <= 2; o <<= 1) {
                    d   += __shfl_xor_sync(0xFFFFFFFFu, d, o);
                    nu  += __shfl_xor_sync(0xFFFFFFFFu, nu, o);
                    cnt += __shfl_xor_sync(0xFFFFFFFFu, cnt, o);
                }
                if ((l & 3) == 0) {
                    int idx = panel * 128 + rg * 32 + mt * 16 + g + j * 8;
                    g_pd[part][idx] = d;
                    g_pn[part][idx] = nu;
                    g_pp[part][idx] = cnt;
                }
            }
        __syncthreads();   // partials written before next segment reuses smem
        cs = ce;
    }
}

// ---------------------------------------------------------------------------
// Kernel 4: per-anchor combine + block partial sums (8 blocks per stem).
// Fixed shared exponent offset -> 8 slots merge by plain addition.
// ---------------------------------------------------------------------------
__global__ void stems_kernel() {
    __shared__ float sd[256];
    __shared__ int   sc[256];
    const int blk = blockIdx.x;
    const int s = blk >> 3, off = (blk & 7) * 512;
    float sum = 0.f; int cnt = 0;
    for (int i = threadIdx.x; i < 512; i += 256) {
        int idx = s * Nn + off + i;
        float d = 0.f, nu = 0.f; int p = 0;
        #pragma unroll
        for (int k = 0; k < 8; ++k) {
            d  += g_pd[k][idx];
            nu += g_pn[k][idx];
            p  += g_pp[k][idx];
        }
        if (p > 0 && p < Mn) { sum += __logf(d) - __logf(nu); cnt++; }
    }
    sd[threadIdx.x] = sum; sc[threadIdx.x] = cnt;
    __syncthreads();
    for (int o = 128; o; o >>= 1) {
        if (threadIdx.x < o) {
            sd[threadIdx.x] += sd[threadIdx.x + o];
            sc[threadIdx.x] += sc[threadIdx.x + o];
        }
        __syncthreads();
    }
    if (threadIdx.x == 0) { g_bsum[blk] = sd[0]; g_bcnt[blk] = sc[0]; }
}

__global__ void final_kernel(float* __restrict__ out) {
    if (threadIdx.x == 0) {
        float loss = 0.f; int ns = 0;
        #pragma unroll
        for (int s = 0; s < Sn; ++s) {
            float sum = 0.f; int cnt = 0;
            #pragma unroll
            for (int b = 0; b < 8; ++b) {
                sum += g_bsum[s * 8 + b];
                cnt += g_bcnt[s * 8 + b];
            }
            if (cnt > 0) { loss += sum / (float)cnt; ns++; }
        }
        out[0] = ns > 0 ? loss / (float)ns : 0.f;
    }
}

// ---------------------------------------------------------------------------
extern "C" void kernel_launch(void* const* d_in, const int* in_sizes, int n_in,
                              void* d_out, int out_size) {
    const float* art  = (const float*)d_in[0];
    const float* ref  = (const float*)d_in[1];
    const void*  mask = d_in[2];
    const float* logT = (const float*)d_in[3];
    (void)in_sizes; (void)n_in; (void)out_size;

    cudaFuncSetAttribute(fused_kernel,
                         cudaFuncAttributeMaxDynamicSharedMemorySize, SM_TOT);

    probe_mask_kernel<<<1, 1024>>>((const unsigned int*)mask);    // idx 0
    norm_kernel<<<(Sn * (Nn + Mn)) / 8, dim3(32, 8)>>>(art, ref); // idx 1
    zero_kernel<<<512, 256>>>();                                  // idx 2
    fused_kernel<<<NCTA, 256, SM_TOT>>>(mask, logT);              // idx 3
    stems_kernel<<<32, 256>>>();                                  // idx 4
    final_kernel<<<1, 32>>>((float*)d_out);                       // idx 5
}